// round 2
// baseline (speedup 1.0000x reference)
#include <cuda_runtime.h>
#include <cuda_bf16.h>
#include <cstdint>

typedef unsigned long long ull;

#define NOUT 24
#define DF 4096
#define NROWS 16384
#define KC 1024
#define NCHUNK 4          // DF / KC
#define THREADS 256
#define WARPS 8
#define RPW 2             // rows per warp
#define RPB (WARPS * RPW) // 16 rows per block
#define HPOST_OFF (NROWS * 4) // 65536
#define HRES_OFF  (NROWS * 8) // 131072

// Fused weights: WGH[j][d] = alpha_j * g[d] * W_j[d]  (bf16), j: 0-3 pre, 4-7 post, 8-23 res
__device__ __nv_bfloat16 WGH[NOUT * DF];
__device__ float BIASD[NOUT];

// ---------------------------------------------------------------------------
// Prep: build fused bf16 weight matrix + bias vector
// ---------------------------------------------------------------------------
__global__ void prep_kernel(const float* __restrict__ g,
                            const float* __restrict__ Wpre,
                            const float* __restrict__ Wpost,
                            const float* __restrict__ Wres,
                            const float* __restrict__ bpre,
                            const float* __restrict__ bpost,
                            const float* __restrict__ bres,
                            const float* __restrict__ apre,
                            const float* __restrict__ apost,
                            const float* __restrict__ ares) {
    int idx = blockIdx.x * blockDim.x + threadIdx.x;
    if (idx < NOUT) {
        BIASD[idx] = (idx < 4) ? bpre[idx] : (idx < 8) ? bpost[idx - 4] : bres[idx - 8];
    }
    if (idx >= NOUT * DF) return;
    int j = idx / DF;
    int d = idx - j * DF;
    float a, w;
    if (j < 4)      { a = apre[0];  w = Wpre[idx]; }
    else if (j < 8) { a = apost[0]; w = Wpost[idx - 4 * DF]; }
    else            { a = ares[0];  w = Wres[idx - 8 * DF]; }
    WGH[idx] = __float2bfloat16(a * g[d] * w);
}

// ---------------------------------------------------------------------------
// Packed fp32x2 helpers (Blackwell)
// ---------------------------------------------------------------------------
__device__ __forceinline__ ull fma2(ull a, ull b, ull c) {
    ull d;
    asm("fma.rn.f32x2 %0, %1, %2, %3;" : "=l"(d) : "l"(a), "l"(b), "l"(c));
    return d;
}

// bf16x2 (lo = k, hi = k+1) -> f32x2 pair
__device__ __forceinline__ ull bf2_to_f32x2(unsigned int b) {
    unsigned int lo = b << 16;
    unsigned int hi = b & 0xFFFF0000u;
    ull d;
    asm("mov.b64 %0, {%1, %2};" : "=l"(d) : "r"(lo), "r"(hi));
    return d;
}

__device__ __forceinline__ float pair_sum(ull v) {
    return __uint_as_float((unsigned int)v) + __uint_as_float((unsigned int)(v >> 32));
}

__device__ __forceinline__ float sigmoidf_acc(float v) {
    return 1.0f / (1.0f + expf(-v));
}

// ---------------------------------------------------------------------------
// Main: fused rmsnorm + 24 dot products. Each warp owns 2 rows; weights are
// staged bf16 in smem per 1024-col chunk and reused by all 8 warps of the block.
// ---------------------------------------------------------------------------
__global__ void __launch_bounds__(THREADS)
main_kernel(const float* __restrict__ X, float* __restrict__ out) {
    __shared__ __nv_bfloat16 wsh[NOUT][KC];   // 48 KB

    const int tid  = threadIdx.x;
    const int lane = tid & 31;
    const int wid  = tid >> 5;
    const int row0 = blockIdx.x * RPB + wid * RPW;
    const float* __restrict__ x0 = X + (size_t)row0 * DF;
    const float* __restrict__ x1 = x0 + DF;

    ull acc0[NOUT], acc1[NOUT];
    ull ss0 = 0ULL, ss1 = 0ULL;
#pragma unroll
    for (int j = 0; j < NOUT; j++) { acc0[j] = 0ULL; acc1[j] = 0ULL; }

    for (int c = 0; c < NCHUNK; c++) {
        // stage weight chunk: NOUT*KC bf16 = 48 KB = 3072 uint4
        {
            const uint4* wsrc = reinterpret_cast<const uint4*>(WGH);
            uint4* wdst = reinterpret_cast<uint4*>(&wsh[0][0]);
#pragma unroll
            for (int i = 0; i < (NOUT * KC / 8) / THREADS; i++) {  // 12 iters
                int idx = i * THREADS + tid;      // uint4 index in tile
                int j  = idx >> 7;                // / (KC/8 = 128)
                int kk = idx & 127;
                wdst[idx] = wsrc[j * (DF / 8) + c * (KC / 8) + kk];
            }
        }
        __syncthreads();

#pragma unroll
        for (int s = 0; s < KC / 256; s++) {      // 4 steps; lane covers 8 consecutive k
            const int kbase = c * KC + s * 256 + lane * 8;
            ulonglong2 a0 = *reinterpret_cast<const ulonglong2*>(x0 + kbase);
            ulonglong2 b0 = *reinterpret_cast<const ulonglong2*>(x0 + kbase + 4);
            ulonglong2 a1 = *reinterpret_cast<const ulonglong2*>(x1 + kbase);
            ulonglong2 b1 = *reinterpret_cast<const ulonglong2*>(x1 + kbase + 4);

            ss0 = fma2(a0.x, a0.x, ss0); ss0 = fma2(a0.y, a0.y, ss0);
            ss0 = fma2(b0.x, b0.x, ss0); ss0 = fma2(b0.y, b0.y, ss0);
            ss1 = fma2(a1.x, a1.x, ss1); ss1 = fma2(a1.y, a1.y, ss1);
            ss1 = fma2(b1.x, b1.x, ss1); ss1 = fma2(b1.y, b1.y, ss1);

            const int kw = s * 256 + lane * 8;
#pragma unroll
            for (int j = 0; j < NOUT; j++) {
                uint4 wb = *reinterpret_cast<const uint4*>(&wsh[j][kw]);
                ull w0 = bf2_to_f32x2(wb.x);
                ull w1 = bf2_to_f32x2(wb.y);
                ull w2 = bf2_to_f32x2(wb.z);
                ull w3 = bf2_to_f32x2(wb.w);
                acc0[j] = fma2(a0.x, w0, acc0[j]);
                acc0[j] = fma2(a0.y, w1, acc0[j]);
                acc0[j] = fma2(b0.x, w2, acc0[j]);
                acc0[j] = fma2(b0.y, w3, acc0[j]);
                acc1[j] = fma2(a1.x, w0, acc1[j]);
                acc1[j] = fma2(a1.y, w1, acc1[j]);
                acc1[j] = fma2(b1.x, w2, acc1[j]);
                acc1[j] = fma2(b1.y, w3, acc1[j]);
            }
        }
        __syncthreads();
    }

    // fold packed pairs, then warp butterfly-reduce (all lanes end with totals)
    float dot0[NOUT], dot1[NOUT];
#pragma unroll
    for (int j = 0; j < NOUT; j++) {
        dot0[j] = pair_sum(acc0[j]);
        dot1[j] = pair_sum(acc1[j]);
    }
    float s0 = pair_sum(ss0);
    float s1 = pair_sum(ss1);
#pragma unroll
    for (int o = 16; o > 0; o >>= 1) {
        s0 += __shfl_xor_sync(0xFFFFFFFFu, s0, o);
        s1 += __shfl_xor_sync(0xFFFFFFFFu, s1, o);
#pragma unroll
        for (int j = 0; j < NOUT; j++) {
            dot0[j] += __shfl_xor_sync(0xFFFFFFFFu, dot0[j], o);
            dot1[j] += __shfl_xor_sync(0xFFFFFFFFu, dot1[j], o);
        }
    }

    if ((lane & 15) == 0) {               // lanes 0 and 16 handle row0/row1
        const int r = lane >> 4;
        const int row = row0 + r;
        const float ssv = r ? s1 : s0;
        const float inv = rsqrtf(ssv * (1.0f / (float)DF) + 1e-6f);
        float h[NOUT];
#pragma unroll
        for (int j = 0; j < NOUT; j++) {
            float d = r ? dot1[j] : dot0[j];
            h[j] = fmaf(inv, d, BIASD[j]);
        }
        float4 o1, o2;
        o1.x = sigmoidf_acc(h[0]); o1.y = sigmoidf_acc(h[1]);
        o1.z = sigmoidf_acc(h[2]); o1.w = sigmoidf_acc(h[3]);
        o2.x = 2.0f * sigmoidf_acc(h[4]); o2.y = 2.0f * sigmoidf_acc(h[5]);
        o2.z = 2.0f * sigmoidf_acc(h[6]); o2.w = 2.0f * sigmoidf_acc(h[7]);
        *reinterpret_cast<float4*>(out + (size_t)row * 4) = o1;
        *reinterpret_cast<float4*>(out + HPOST_OFF + (size_t)row * 4) = o2;
#pragma unroll
        for (int q = 0; q < 4; q++) {
            float4 o3;
            o3.x = h[8 + q * 4 + 0]; o3.y = h[8 + q * 4 + 1];
            o3.z = h[8 + q * 4 + 2]; o3.w = h[8 + q * 4 + 3];
            *reinterpret_cast<float4*>(out + HRES_OFF + (size_t)row * 16 + q * 4) = o3;
        }
    }
}

// ---------------------------------------------------------------------------
// Sinkhorn: in-place on the hres region of d_out. One thread per row; the 4x4
// matrix lives in registers. Column-normalize then row-normalize, 20 iters.
// ---------------------------------------------------------------------------
__global__ void sinkhorn_kernel(float* __restrict__ out) {
    int row = blockIdx.x * blockDim.x + threadIdx.x;
    if (row >= NROWS) return;
    float* base = out + HRES_OFF + (size_t)row * 16;
    float p[16];
#pragma unroll
    for (int q = 0; q < 4; q++) {
        float4 v = reinterpret_cast<const float4*>(base)[q];
        p[q * 4 + 0] = v.x; p[q * 4 + 1] = v.y;
        p[q * 4 + 2] = v.z; p[q * 4 + 3] = v.w;
    }
#pragma unroll
    for (int i = 0; i < 16; i++)
        p[i] = expf(fminf(fmaxf(p[i], -15.0f), 15.0f));

    for (int it = 0; it < 20; it++) {
#pragma unroll
        for (int cc = 0; cc < 4; cc++) {          // column sums (axis=-2)
            float s = p[cc] + p[4 + cc] + p[8 + cc] + p[12 + cc] + 1e-6f;
            float rI = 1.0f / s;
            p[cc] *= rI; p[4 + cc] *= rI; p[8 + cc] *= rI; p[12 + cc] *= rI;
        }
#pragma unroll
        for (int rr = 0; rr < 4; rr++) {          // row sums (axis=-1)
            float s = p[rr * 4] + p[rr * 4 + 1] + p[rr * 4 + 2] + p[rr * 4 + 3] + 1e-6f;
            float rI = 1.0f / s;
            p[rr * 4] *= rI; p[rr * 4 + 1] *= rI; p[rr * 4 + 2] *= rI; p[rr * 4 + 3] *= rI;
        }
    }
#pragma unroll
    for (int q = 0; q < 4; q++) {
        float4 v;
        v.x = p[q * 4 + 0]; v.y = p[q * 4 + 1];
        v.z = p[q * 4 + 2]; v.w = p[q * 4 + 3];
        reinterpret_cast<float4*>(base)[q] = v;
    }
}

// ---------------------------------------------------------------------------
// Launch
// ---------------------------------------------------------------------------
extern "C" void kernel_launch(void* const* d_in, const int* in_sizes, int n_in,
                              void* d_out, int out_size) {
    const float* X     = (const float*)d_in[0];
    const float* g     = (const float*)d_in[1];
    const float* Wpre  = (const float*)d_in[2];
    const float* Wpost = (const float*)d_in[3];
    const float* Wres  = (const float*)d_in[4];
    const float* bpre  = (const float*)d_in[5];
    const float* bpost = (const float*)d_in[6];
    const float* bres  = (const float*)d_in[7];
    const float* apre  = (const float*)d_in[8];
    const float* apost = (const float*)d_in[9];
    const float* ares  = (const float*)d_in[10];
    float* out = (float*)d_out;

    prep_kernel<<<(NOUT * DF + 255) / 256, 256>>>(g, Wpre, Wpost, Wres,
                                                  bpre, bpost, bres,
                                                  apre, apost, ares);
    main_kernel<<<NROWS / RPB, THREADS>>>(X, out);
    sinkhorn_kernel<<<(NROWS + 255) / 256, 256>>>(out);
}

// round 5
// speedup vs baseline: 1.0266x; 1.0266x over previous
#include <cuda_runtime.h>
#include <cuda_bf16.h>
#include <cstdint>

#define NROWS 16384
#define DF    4096
#define NOUT  24
#define MROWS 64            // rows per CTA
#define THREADS 128
#define WARPS 4
#define KCH   64            // k per chunk
#define NCHUNK (DF / KCH)   // 64
#define NKG   4             // k-groups of 16 per chunk
#define NT    3             // n-tiles of 8 (24 outputs)
#define HPOST_OFF (NROWS * 4)
#define HRES_OFF  (NROWS * 8)

// Fused weights in mma B-fragment layout:
// WB[kg(256)][nt(3)][lane(32)] : uint2
//   .x = bf16x2( w[n][k0],   w[n][k0+1] )   (lo = k0)
//   .y = bf16x2( w[n][k0+8], w[n][k0+9] )
// with n = nt*8 + lane/4, k0 = kg*16 + (lane%4)*2, w[n][k] = alpha_n*g[k]*W_n[k]
__device__ uint2 WB[256 * NT * 32];
__device__ float BIASD[NOUT];

// ---------------------------------------------------------------------------
__device__ __forceinline__ uint32_t pack_bf2(float lo, float hi) {
    uint32_t d;
    asm("cvt.rn.bf16x2.f32 %0, %1, %2;" : "=r"(d) : "f"(hi), "f"(lo));
    return d;
}

__device__ __forceinline__ void mma_bf16(float* c, const uint32_t* a, uint2 b) {
    asm volatile(
        "mma.sync.aligned.m16n8k16.row.col.f32.bf16.bf16.f32 "
        "{%0,%1,%2,%3}, {%4,%5,%6,%7}, {%8,%9}, {%0,%1,%2,%3};"
        : "+f"(c[0]), "+f"(c[1]), "+f"(c[2]), "+f"(c[3])
        : "r"(a[0]), "r"(a[1]), "r"(a[2]), "r"(a[3]), "r"(b.x), "r"(b.y));
}

__device__ __forceinline__ float sigmoidf_acc(float v) {
    return 1.0f / (1.0f + expf(-v));
}

// ---------------------------------------------------------------------------
// Prep: fused weights -> B fragments, plus biases
// ---------------------------------------------------------------------------
__global__ void prep_kernel(const float* __restrict__ g,
                            const float* __restrict__ Wpre,
                            const float* __restrict__ Wpost,
                            const float* __restrict__ Wres,
                            const float* __restrict__ bpre,
                            const float* __restrict__ bpost,
                            const float* __restrict__ bres,
                            const float* __restrict__ apre,
                            const float* __restrict__ apost,
                            const float* __restrict__ ares) {
    int idx = blockIdx.x * blockDim.x + threadIdx.x;
    if (idx < NOUT) {
        BIASD[idx] = (idx < 4) ? bpre[idx] : (idx < 8) ? bpost[idx - 4] : bres[idx - 8];
    }
    if (idx >= 256 * NT * 32) return;
    int kg   = idx / (NT * 32);
    int rem  = idx - kg * (NT * 32);
    int nt   = rem >> 5;
    int lane = rem & 31;
    int n  = nt * 8 + (lane >> 2);
    int k0 = kg * 16 + (lane & 3) * 2;

    float a;
    const float* wrow;
    if (n < 4)      { a = apre[0];  wrow = Wpre  + (size_t)n * DF; }
    else if (n < 8) { a = apost[0]; wrow = Wpost + (size_t)(n - 4) * DF; }
    else            { a = ares[0];  wrow = Wres  + (size_t)(n - 8) * DF; }

    float w00 = a * g[k0]     * wrow[k0];
    float w01 = a * g[k0 + 1] * wrow[k0 + 1];
    float w80 = a * g[k0 + 8] * wrow[k0 + 8];
    float w81 = a * g[k0 + 9] * wrow[k0 + 9];
    uint2 u;
    u.x = pack_bf2(w00, w01);
    u.y = pack_bf2(w80, w81);
    WB[idx] = u;
}

// ---------------------------------------------------------------------------
// Main: streaming bf16 tensor-core GEMM + rmsnorm + sigmoid + sinkhorn
// ---------------------------------------------------------------------------
__global__ void __launch_bounds__(THREADS)
main_kernel(const float* __restrict__ X, float* __restrict__ out) {
    __shared__ __align__(16) __nv_bfloat16 Ash[2][MROWS][KCH]; // 2 x 8 KB
    __shared__ uint2 Bsh[2][NKG][NT][32];                       // 2 x 3 KB
    __shared__ float ssm[THREADS];
    __shared__ float hsm[MROWS][25];

    const int tid  = threadIdx.x;
    const int lane = tid & 31;
    const int wid  = tid >> 5;

    const int rowL = tid >> 1;              // 0..63
    const int kofs = (tid & 1) * 32;        // float offset within chunk
    const float* xp = X + ((size_t)blockIdx.x * MROWS + rowL) * DF + kofs;

    float xr[32];
#pragma unroll
    for (int i = 0; i < 8; i++)
        *reinterpret_cast<float4*>(&xr[i * 4]) = *reinterpret_cast<const float4*>(xp + i * 4);

    float ssp = 0.0f;
    float acc[NT][4];
#pragma unroll
    for (int nt = 0; nt < NT; nt++)
#pragma unroll
        for (int q = 0; q < 4; q++) acc[nt][q] = 0.0f;

    // precompute swizzled STS base: row*128, col base = kofs*2 bytes
    char* ashBase0 = reinterpret_cast<char*>(&Ash[0][0][0]);
    char* ashBase1 = reinterpret_cast<char*>(&Ash[1][0][0]);

    for (int c = 0; c < NCHUNK; c++) {
        const int b = c & 1;
        char* ab = b ? ashBase1 : ashBase0;

        // sumsq + convert + swizzled store (4 x STS.128)
#pragma unroll
        for (int i2 = 0; i2 < 4; i2++) {
            const float* f = &xr[i2 * 8];
            uint4 u;
            u.x = pack_bf2(f[0], f[1]);
            u.y = pack_bf2(f[2], f[3]);
            u.z = pack_bf2(f[4], f[5]);
            u.w = pack_bf2(f[6], f[7]);
#pragma unroll
            for (int q = 0; q < 8; q++) ssp = fmaf(f[q], f[q], ssp);
            int kb = kofs * 2 + i2 * 16;
            int sw = kb ^ ((rowL & 7) << 4);
            *reinterpret_cast<uint4*>(ab + rowL * 128 + sw) = u;
        }

        // stage B chunk: 384 uint2, 128 threads x 3
        {
            uint2* bd = &Bsh[b][0][0][0];
            const uint2* bs = &WB[c * (NKG * NT * 32)];
#pragma unroll
            for (int i = 0; i < 3; i++) bd[i * THREADS + tid] = bs[i * THREADS + tid];
        }
        __syncthreads();

        // prefetch next chunk while mma runs
        if (c < NCHUNK - 1) {
            xp += KCH;
#pragma unroll
            for (int i = 0; i < 8; i++)
                *reinterpret_cast<float4*>(&xr[i * 4]) =
                    *reinterpret_cast<const float4*>(xp + i * 4);
        }

        // mma phase: warp rows R = wid*16
#pragma unroll
        for (int kg = 0; kg < NKG; kg++) {
            int r  = (wid << 4) + (lane & 7) + (lane & 8);
            int kb = kg * 32 + ((lane >> 4) << 4);
            int sw = kb ^ ((r & 7) << 4);
            uint32_t sa = (uint32_t)__cvta_generic_to_shared(ab + r * 128 + sw);
            uint32_t a0, a1, a2, a3;
            asm volatile("ldmatrix.sync.aligned.m8n8.x4.shared.b16 {%0,%1,%2,%3}, [%4];"
                         : "=r"(a0), "=r"(a1), "=r"(a2), "=r"(a3) : "r"(sa));
            uint32_t afr[4] = {a0, a1, a2, a3};
#pragma unroll
            for (int nt = 0; nt < NT; nt++) {
                uint2 bf = Bsh[b][kg][nt][lane];
                mma_bf16(acc[nt], afr, bf);
            }
        }
        __syncthreads();
    }

    // ---- epilogue ----
    ssm[tid] = ssp;
    {
        int r0 = (wid << 4) + (lane >> 2);
#pragma unroll
        for (int nt = 0; nt < NT; nt++) {
            int n0 = nt * 8 + (lane & 3) * 2;
            hsm[r0][n0]     = acc[nt][0];
            hsm[r0][n0 + 1] = acc[nt][1];
            hsm[r0 + 8][n0]     = acc[nt][2];
            hsm[r0 + 8][n0 + 1] = acc[nt][3];
        }
    }
    __syncthreads();

    if (tid < MROWS) {
        const int row = blockIdx.x * MROWS + tid;
        float ss = ssm[2 * tid] + ssm[2 * tid + 1];
        float inv = rsqrtf(ss * (1.0f / (float)DF) + 1e-6f);

        float h[NOUT];
#pragma unroll
        for (int j = 0; j < NOUT; j++)
            h[j] = fmaf(inv, hsm[tid][j], BIASD[j]);

        float4 o1, o2;
        o1.x = sigmoidf_acc(h[0]); o1.y = sigmoidf_acc(h[1]);
        o1.z = sigmoidf_acc(h[2]); o1.w = sigmoidf_acc(h[3]);
        o2.x = 2.0f * sigmoidf_acc(h[4]); o2.y = 2.0f * sigmoidf_acc(h[5]);
        o2.z = 2.0f * sigmoidf_acc(h[6]); o2.w = 2.0f * sigmoidf_acc(h[7]);
        *reinterpret_cast<float4*>(out + (size_t)row * 4) = o1;
        *reinterpret_cast<float4*>(out + HPOST_OFF + (size_t)row * 4) = o2;

        // Sinkhorn on h[8..23] (4x4, registers)
        float p[16];
#pragma unroll
        for (int i = 0; i < 16; i++)
            p[i] = expf(fminf(fmaxf(h[8 + i], -15.0f), 15.0f));
#pragma unroll 1
        for (int it = 0; it < 20; it++) {
#pragma unroll
            for (int cc = 0; cc < 4; cc++) {
                float s = p[cc] + p[4 + cc] + p[8 + cc] + p[12 + cc] + 1e-6f;
                float rI = __fdividef(1.0f, s);
                p[cc] *= rI; p[4 + cc] *= rI; p[8 + cc] *= rI; p[12 + cc] *= rI;
            }
#pragma unroll
            for (int rr = 0; rr < 4; rr++) {
                float s = p[rr * 4] + p[rr * 4 + 1] + p[rr * 4 + 2] + p[rr * 4 + 3] + 1e-6f;
                float rI = __fdividef(1.0f, s);
                p[rr * 4] *= rI; p[rr * 4 + 1] *= rI; p[rr * 4 + 2] *= rI; p[rr * 4 + 3] *= rI;
            }
        }
#pragma unroll
        for (int q = 0; q < 4; q++) {
            float4 v;
            v.x = p[q * 4 + 0]; v.y = p[q * 4 + 1];
            v.z = p[q * 4 + 2]; v.w = p[q * 4 + 3];
            *reinterpret_cast<float4*>(out + HRES_OFF + (size_t)row * 16 + q * 4) = v;
        }
    }
}

// ---------------------------------------------------------------------------
extern "C" void kernel_launch(void* const* d_in, const int* in_sizes, int n_in,
                              void* d_out, int out_size) {
    const float* X     = (const float*)d_in[0];
    const float* g     = (const float*)d_in[1];
    const float* Wpre  = (const float*)d_in[2];
    const float* Wpost = (const float*)d_in[3];
    const float* Wres  = (const float*)d_in[4];
    const float* bpre  = (const float*)d_in[5];
    const float* bpost = (const float*)d_in[6];
    const float* bres  = (const float*)d_in[7];
    const float* apre  = (const float*)d_in[8];
    const float* apost = (const float*)d_in[9];
    const float* ares  = (const float*)d_in[10];
    float* out = (float*)d_out;

    prep_kernel<<<(256 * NT * 32 + 255) / 256, 256>>>(g, Wpre, Wpost, Wres,
                                                      bpre, bpost, bres,
                                                      apre, apost, ares);
    main_kernel<<<NROWS / MROWS, THREADS>>>(X, out);
}